// round 6
// baseline (speedup 1.0000x reference)
#include <cuda_runtime.h>
#include <cuda_bf16.h>

#define NMAX 10
#define LP1  8
#define NZ   (NMAX * LP1)
#define THR  0.0625f
#define EDGES_PER_BLK 32
#define PAD 88                     // floats per edge in smem (80 + 8 pad)

// Compute mapping: thread = (edge, n), all 8 l's with compile-time recurrence
// depth (rounds 4-5, validated). NEW: results staged in smem, then streamed
// out as fully-coalesced STG.128 — removes the 8x store-wavefront inflation
// of the stride-40B direct stores (L1 was 49% busy on stores alone).

__device__ __forceinline__ float jl_fast(int l, float x) {
    float s, c, u;
    asm("sin.approx.f32 %0, %1;" : "=f"(s) : "f"(x));
    asm("cos.approx.f32 %0, %1;" : "=f"(c) : "f"(x));
    asm("rcp.approx.f32 %0, %1;" : "=f"(u) : "f"(x));
    float jm1 = s * u;                       // j0
    if (l == 0) return jm1;
    float j = fmaf(jm1, u, -(c * u));        // j1
    #pragma unroll
    for (int k = 2; k <= 7; ++k) {
        if (k > l) break;
        float jn = fmaf((float)(2 * k - 1) * u, j, -jm1);
        jm1 = j; j = jn;
    }
    return j;
}

__device__ __forceinline__ float jl_exact(int l, float x) {
    const double xd = (double)x;
    const double x2 = xd * xd;
    double sp = fma(x2,  1.0/6227020800.0, -1.0/39916800.0);
    sp = fma(x2, sp,  1.0/362880.0);
    sp = fma(x2, sp, -1.0/5040.0);
    sp = fma(x2, sp,  1.0/120.0);
    sp = fma(x2, sp, -1.0/6.0);
    const float s = __double2float_rn(fma(xd * x2, sp, xd));
    double cp = fma(x2, -1.0/87178291200.0, 1.0/479001600.0);
    cp = fma(x2, cp, -1.0/3628800.0);
    cp = fma(x2, cp,  1.0/40320.0);
    cp = fma(x2, cp, -1.0/720.0);
    cp = fma(x2, cp,  1.0/24.0);
    cp = fma(x2, cp, -0.5);
    const float c = __double2float_rn(fma(x2, cp, 1.0));

    float jm1 = __fdiv_rn(s, x);                                   // j0
    if (l == 0) return jm1;
    const float xx = __fmul_rn(x, x);
    float j = __fsub_rn(__fdiv_rn(s, xx), __fdiv_rn(c, x));        // j1
    #pragma unroll
    for (int k = 2; k <= 7; ++k) {
        if (k > l) break;
        float jn = __fsub_rn(__fmul_rn(__fdiv_rn((float)(2 * k - 1), x), j), jm1);
        jm1 = j; j = jn;
    }
    return j;
}

__global__ void __launch_bounds__(320)
radial_basis_kernel(const float* __restrict__ r,
                    const float* __restrict__ zeros,   // [NMAX, LP1]
                    float* __restrict__ out,           // [N, LP1, NMAX]
                    int nEdges)
{
    __shared__ float sm[EDGES_PER_BLK * PAD];

    const int tid    = threadIdx.x;          // 320 = 32 edges * 10 n
    const int eLocal = tid / NMAX;
    const int n      = tid - eLocal * NMAX;
    const int i      = blockIdx.x * EDGES_PER_BLK + eLocal;

    if (i < nEdges) {
        const float rv = __ldg(&r[i]);
        const float4 za = __ldg((const float4*)(zeros + n * LP1));
        const float4 zb = __ldg((const float4*)(zeros + n * LP1) + 1);
        const float z[8] = {za.x, za.y, za.z, za.w, zb.x, zb.y, zb.z, zb.w};

        float* o = sm + eLocal * PAD + n;
        const float x0 = __fmul_rn(__fmul_rn(z[0], rv), 0.2f);

        if (x0 >= THR) {
            #pragma unroll
            for (int l = 0; l < LP1; ++l) {
                const float x = __fmul_rn(__fmul_rn(z[l], rv), 0.2f);
                o[l * NMAX] = jl_fast(l, x);
            }
        } else {
            #pragma unroll
            for (int l = 0; l < LP1; ++l) {
                const float x = __fmul_rn(__fmul_rn(z[l], rv), 0.2f);
                o[l * NMAX] = (x < THR) ? jl_exact(l, x) : jl_fast(l, x);
            }
        }
    }
    __syncthreads();

    // Coalesced epilogue: 32 edges * 80 floats = 640 float4 per block,
    // 2 per thread; smem addr remaps around the PAD.
    float4* o4 = (float4*)(out + (size_t)blockIdx.x * EDGES_PER_BLK * NZ);
    #pragma unroll
    for (int k = 0; k < 2; ++k) {
        const int j4 = tid + k * 320;              // 0..639
        const int e  = j4 / (NZ / 4);              // /20
        const int w  = j4 - e * (NZ / 4);
        if (blockIdx.x * EDGES_PER_BLK + e < nEdges) {
            const float4 v = *((const float4*)(sm + e * PAD) + w);
            o4[j4] = v;
        }
    }
}

extern "C" void kernel_launch(void* const* d_in, const int* in_sizes, int n_in,
                              void* d_out, int out_size)
{
    const float* r     = (const float*)d_in[0];
    const float* zeros = (const float*)d_in[1];
    float* out         = (float*)d_out;
    const int n = in_sizes[0];

    const int blocks = (n + EDGES_PER_BLK - 1) / EDGES_PER_BLK;
    radial_basis_kernel<<<blocks, 320>>>(r, zeros, out, n);
}